// round 11
// baseline (speedup 1.0000x reference)
#include <cuda_runtime.h>
#include <cuda.h>
#include <cuda_fp16.h>
#include <cstdint>
#include <cstring>

// ---------------- problem constants ----------------
#define TOKENS 8192
#define IN_F   4096
#define OUT_F  11008

// ---------------- GEMM tiling (2 CTAs/SM) ----------------
constexpr int TILE_M = 128;            // CTA M
constexpr int TILE_N = 128;            // CTA N
constexpr int KC     = 64;             // K elems per stage (one 64-col SW128 chunk)
constexpr int NKIT   = IN_F / KC;      // 64  (power of two: f>>6 / f&63)
constexpr int S      = 3;              // pipeline stages

constexpr int NT_M   = TOKENS / TILE_M;   // 64 (power of two)
constexpr int NT_N   = OUT_F / TILE_N;    // 86
constexpr int NTILES = NT_M * NT_N;       // 5504

// ---------------- SMEM layout ----------------
constexpr int SMEM_TILES   = 1024;                 // 1024-aligned for SW128
constexpr int A_CHUNK      = TILE_M * 128;         // 16384 (128 rows x 128B)
constexpr int B_CHUNK      = TILE_N * 128;         // 16384
constexpr int STAGE_BYTES  = A_CHUNK + B_CHUNK;    // 32768
constexpr int SMEM_TOTAL   = SMEM_TILES + S * STAGE_BYTES;  // 99328 (x2 CTAs = 198656)

// ---------------- scratch (fp16 copies) ----------------
__device__ __align__(1024) __half g_x16[(size_t)TOKENS * IN_F];
__device__ __align__(1024) __half g_w16[(size_t)OUT_F * IN_F];

// ---------------- PTX helpers ----------------
__device__ __forceinline__ uint32_t smem_u32(const void* p) {
    uint32_t a;
    asm("{ .reg .u64 t; cvta.to.shared.u64 t, %1; cvt.u32.u64 %0, t; }" : "=r"(a) : "l"(p));
    return a;
}

#define MBAR_INIT(a, c) \
    asm volatile("mbarrier.init.shared.b64 [%0], %1;" :: "r"(a), "r"((uint32_t)(c)) : "memory")

#define MBAR_EXPECT_TX(a, b) \
    asm volatile("mbarrier.arrive.expect_tx.shared.b64 _, [%0], %1;" :: "r"(a), "r"((uint32_t)(b)) : "memory")

#define MBAR_ARRIVE(a) \
    asm volatile("mbarrier.arrive.shared.b64 _, [%0];" :: "r"(a) : "memory")

#define MBAR_WAIT(a, ph) do {                                                          \
    uint32_t _m = (a); uint32_t _p = (uint32_t)(ph); uint32_t _d;                      \
    asm volatile("{\n .reg .pred p;\n"                                                 \
                 " mbarrier.try_wait.parity.acquire.cta.shared::cta.b64 p, [%1], %2;\n" \
                 " selp.b32 %0, 1, 0, p;\n}" : "=r"(_d) : "r"(_m), "r"(_p) : "memory"); \
    if (!_d) {                                                                         \
        asm volatile("{\n .reg .pred P1;\n"                                            \
                     "WL_%=:\n"                                                         \
                     " mbarrier.try_wait.parity.acquire.cta.shared::cta.b64 P1, [%0], %1, 0x989680;\n" \
                     " @P1 bra.uni WD_%=;\n bra.uni WL_%=;\nWD_%=:\n}"                  \
                     :: "r"(_m), "r"(_p) : "memory");                                   \
    }                                                                                   \
} while (0)

__device__ __forceinline__ void tma2d(uint32_t dst, const CUtensorMap* m, int cx, int cy,
                                      uint32_t bar) {
    asm volatile(
        "cp.async.bulk.tensor.2d.shared::cta.global.tile.mbarrier::complete_tx::bytes "
        "[%0], [%1, {%2, %3}], [%4];"
        :: "r"(dst), "l"(m), "r"(cx), "r"(cy), "r"(bar) : "memory");
}

__device__ __forceinline__ void ldsm4(uint32_t* r, uint32_t addr) {
    asm volatile("ldmatrix.sync.aligned.m8n8.x4.shared.b16 {%0,%1,%2,%3}, [%4];"
                 : "=r"(r[0]), "=r"(r[1]), "=r"(r[2]), "=r"(r[3]) : "r"(addr));
}

__device__ __forceinline__ void mma16816(float* c, const uint32_t* a, const uint32_t* b) {
    asm volatile(
        "mma.sync.aligned.m16n8k16.row.col.f32.f16.f16.f32 "
        "{%0,%1,%2,%3}, {%4,%5,%6,%7}, {%8,%9}, {%0,%1,%2,%3};"
        : "+f"(c[0]), "+f"(c[1]), "+f"(c[2]), "+f"(c[3])
        : "r"(a[0]), "r"(a[1]), "r"(a[2]), "r"(a[3]), "r"(b[0]), "r"(b[1]));
}

// SW128: XOR 16B-column index with (row & 7)
__device__ __forceinline__ uint32_t sw128(uint32_t off) {
    return off ^ ((off >> 3) & 0x70);
}

// ---------------- fused conversion kernel (single launch) ----------------
// x: fp32 -> fp16 ; w: int32 (harness-upcast int8) -> fp16
__global__ void __launch_bounds__(256) cvt_all_kernel(const float4* __restrict__ x,
                                                      uint2* __restrict__ ox, int n4x,
                                                      const int4* __restrict__ w,
                                                      uint2* __restrict__ ow, int n4w) {
    int i = blockIdx.x * blockDim.x + threadIdx.x;
    if (i < n4x) {
        float4 v = x[i];
        __half2 a = __floats2half2_rn(v.x, v.y);
        __half2 b = __floats2half2_rn(v.z, v.w);
        uint2 u;
        memcpy(&u.x, &a, 4);
        memcpy(&u.y, &b, 4);
        ox[i] = u;
    } else {
        int j = i - n4x;
        if (j < n4w) {
            int4 v = w[j];
            __half2 a = __floats2half2_rn((float)v.x, (float)v.y);
            __half2 b = __floats2half2_rn((float)v.z, (float)v.w);
            uint2 u;
            memcpy(&u.x, &a, 4);
            memcpy(&u.y, &b, 4);
            ow[j] = u;
        }
    }
}

// ---------------- main GEMM kernel (persistent, 2 CTAs/SM) ----------------
__global__ void __launch_bounds__(256, 2)
qlin_gemm_kernel(const __grid_constant__ CUtensorMap tmA,
                 const __grid_constant__ CUtensorMap tmB,
                 const float* __restrict__ scales,
                 const float* __restrict__ bias,
                 float* __restrict__ out) {
    extern __shared__ __align__(1024) char smem[];
    const uint32_t sb = smem_u32(smem);
    const int tid  = threadIdx.x;
    const int wid  = tid >> 5;
    const int lane = tid & 31;
    const int warp_m = wid >> 1;     // 0..3  (32 rows each)
    const int warp_n = wid & 1;      // 0..1  (64 cols each)

    const int bid  = blockIdx.x;
    const int ncta = gridDim.x;

#define FULL_BAR(s)  (sb + (s) * 16)
#define EMPTY_BAR(s) (sb + (s) * 16 + 8)
#define A_OFF(s)     (SMEM_TILES + (s) * STAGE_BYTES)
#define B_OFF(s)     (A_OFF(s) + A_CHUNK)

    if (tid == 0) {
        #pragma unroll
        for (int s = 0; s < S; s++) {
            MBAR_INIT(FULL_BAR(s), 1);   // expect_tx arrive by producer
            MBAR_INIT(EMPTY_BAR(s), 8);  // one arrive per warp
        }
    }
    __syncthreads();   // barrier init visible

    const int nt_mine  = (NTILES - bid + ncta - 1) / ncta;
    const int my_total = nt_mine * NKIT;

    // prologue: issue global stages 0, 1 (S-1 = 2 deep)
    if (tid == 0) {
        #pragma unroll
        for (int f = 0; f < 2; f++) {
            int ft = bid;                       // both belong to first tile (NKIT=64 > 2)
            int fm = (ft & (NT_M - 1)) * TILE_M;
            int fn = (ft >> 6) * TILE_N;
            MBAR_EXPECT_TX(FULL_BAR(f), STAGE_BYTES);
            tma2d(sb + A_OFF(f), &tmA, f * KC, fm, FULL_BAR(f));
            tma2d(sb + B_OFF(f), &tmB, f * KC, fn, FULL_BAR(f));
        }
    }

    // per-lane ldmatrix base byte offsets (chunk-relative, before swizzle)
    uint32_t aRow[2], bRow[4];
    #pragma unroll
    for (int mt = 0; mt < 2; mt++)
        aRow[mt] = (uint32_t)(warp_m * 32 + mt * 16 + (lane & 15)) * 128 +
                   ((lane >> 4) << 4);
    #pragma unroll
    for (int n2 = 0; n2 < 4; n2++)
        bRow[n2] = (uint32_t)(warp_n * 64 + n2 * 16 + (lane & 7) + ((lane >> 4) << 3)) * 128 +
                   (((lane >> 3) & 1) << 4);

    float acc[2][8][4];
    #pragma unroll
    for (int mt = 0; mt < 2; mt++)
        #pragma unroll
        for (int nt = 0; nt < 8; nt++)
            #pragma unroll
            for (int j = 0; j < 4; j++) acc[mt][nt][j] = 0.f;

    int g = 0;                 // continuous global stage counter
    int cst = 0, cph = 0;      // consumer ring pos + parity
    int pst = 2, eph = 1;      // producer ring pos (for f=g+2) + empty-wait parity
    for (int ti = 0; ti < nt_mine; ti++) {
        const int t      = bid + ti * ncta;
        const int tile_m = (t & (NT_M - 1)) * TILE_M;
        const int tile_n = (t >> 6) * TILE_N;

        for (int kt = 0; kt < NKIT; kt++, g++) {
            // producer: issue fill for global stage g+2 (may belong to next tile)
            if (tid == 0) {
                int f = g + 2;
                if (f < my_total) {
                    if (f >= S) MBAR_WAIT(EMPTY_BAR(pst), eph);
                    int ft  = bid + (f >> 6) * ncta;
                    int fkt = (f & (NKIT - 1)) * KC;
                    int fm  = (ft & (NT_M - 1)) * TILE_M;
                    int fn  = (ft >> 6) * TILE_N;
                    MBAR_EXPECT_TX(FULL_BAR(pst), STAGE_BYTES);
                    tma2d(sb + A_OFF(pst), &tmA, fkt, fm, FULL_BAR(pst));
                    tma2d(sb + B_OFF(pst), &tmB, fkt, fn, FULL_BAR(pst));
                    if (++pst == S) { pst = 0; eph ^= 1; }
                }
            }

            MBAR_WAIT(FULL_BAR(cst), cph);

            const uint32_t aT = sb + A_OFF(cst);
            const uint32_t bT = sb + B_OFF(cst);

            #pragma unroll
            for (int kk = 0; kk < 4; kk++) {
                uint32_t a[2][4], b[4][4];
                #pragma unroll
                for (int mt = 0; mt < 2; mt++)
                    ldsm4(a[mt], aT + sw128(aRow[mt] + kk * 32));
                #pragma unroll
                for (int n2 = 0; n2 < 4; n2++)
                    ldsm4(b[n2], bT + sw128(bRow[n2] + kk * 32));
                #pragma unroll
                for (int mt = 0; mt < 2; mt++)
                    #pragma unroll
                    for (int nt = 0; nt < 8; nt++)
                        mma16816(acc[mt][nt], a[mt], &b[nt >> 1][(nt & 1) * 2]);
            }

            if (lane == 0) MBAR_ARRIVE(EMPTY_BAR(cst));
            if (++cst == S) { cst = 0; cph ^= 1; }
        }

        // ---------------- per-tile epilogue (next tile's TMA already in flight) ----
        #pragma unroll
        for (int nt = 0; nt < 8; nt++) {
            const int lc = tile_n + warp_n * 64 + nt * 8 + 2 * (lane & 3);
            const float s0 = __ldg(scales + lc);
            const float s1 = __ldg(scales + lc + 1);
            const float b0 = __ldg(bias + lc);
            const float b1 = __ldg(bias + lc + 1);
            #pragma unroll
            for (int mt = 0; mt < 2; mt++) {
                const int r0 = tile_m + warp_m * 32 + mt * 16 + (lane >> 2);
                float* p0 = out + (size_t)r0 * OUT_F + lc;
                float* p1 = p0 + (size_t)8 * OUT_F;
                float2 v0, v1;
                v0.x = fmaf(acc[mt][nt][0], s0, b0);
                v0.y = fmaf(acc[mt][nt][1], s1, b1);
                v1.x = fmaf(acc[mt][nt][2], s0, b0);
                v1.y = fmaf(acc[mt][nt][3], s1, b1);
                __stcs(reinterpret_cast<float2*>(p0), v0);
                __stcs(reinterpret_cast<float2*>(p1), v1);
            }
        }

        // reset accumulators for next tile
        #pragma unroll
        for (int mt = 0; mt < 2; mt++)
            #pragma unroll
            for (int nt = 0; nt < 8; nt++)
                #pragma unroll
                for (int j = 0; j < 4; j++) acc[mt][nt][j] = 0.f;
    }
}

// ---------------- host: tensormap + launch ----------------
typedef CUresult (*PFN_tmapenc)(CUtensorMap*, CUtensorMapDataType, cuuint32_t, void*,
                                const cuuint64_t*, const cuuint64_t*, const cuuint32_t*,
                                const cuuint32_t*, CUtensorMapInterleave, CUtensorMapSwizzle,
                                CUtensorMapL2promotion, CUtensorMapFloatOOBfill);

static PFN_tmapenc get_tmap_fn() {
    void* fp = nullptr;
    cudaDriverEntryPointQueryResult qr;
#if CUDART_VERSION >= 12050
    cudaGetDriverEntryPointByVersion("cuTensorMapEncodeTiled", &fp, 12000, cudaEnableDefault, &qr);
#else
    cudaGetDriverEntryPoint("cuTensorMapEncodeTiled", &fp, cudaEnableDefault, &qr);
#endif
    return (PFN_tmapenc)fp;
}

static void make_map(PFN_tmapenc fn, CUtensorMap* m, void* base, uint64_t d0, uint64_t d1,
                     uint32_t b0, uint32_t b1) {
    cuuint64_t dims[2]    = {d0, d1};
    cuuint64_t strides[1] = {d0 * 2};  // bytes (fp16)
    cuuint32_t box[2]     = {b0, b1};
    cuuint32_t es[2]      = {1, 1};
    fn(m, CU_TENSOR_MAP_DATA_TYPE_FLOAT16, 2, base, dims, strides, box, es,
       CU_TENSOR_MAP_INTERLEAVE_NONE, CU_TENSOR_MAP_SWIZZLE_128B,
       CU_TENSOR_MAP_L2_PROMOTION_L2_128B, CU_TENSOR_MAP_FLOAT_OOB_FILL_NONE);
}

extern "C" void kernel_launch(void* const* d_in, const int* in_sizes, int n_in,
                              void* d_out, int out_size) {
    const float* x      = (const float*)d_in[0];
    const int4*  w      = (const int4*)d_in[1];   // int32 weights, 4 per int4
    const float* scales = (const float*)d_in[2];
    const float* bias   = (const float*)d_in[3];
    float*       out    = (float*)d_out;

    void* xp = nullptr;
    void* wp = nullptr;
    cudaGetSymbolAddress(&xp, g_x16);
    cudaGetSymbolAddress(&wp, g_w16);

    // fused fp16 conversion pre-pass: ONE launch so the GEMM is every 2nd kernel
    {
        int n4x = TOKENS * IN_F / 4;
        int n4w = OUT_F * IN_F / 4;
        int tot = n4x + n4w;
        cvt_all_kernel<<<(tot + 255) / 256, 256>>>((const float4*)x, (uint2*)xp, n4x,
                                                   w, (uint2*)wp, n4w);
    }

    PFN_tmapenc fn = get_tmap_fn();
    CUtensorMap tmA, tmB;
    make_map(fn, &tmA, xp, IN_F, TOKENS, 64, TILE_M);  // A: [K, M], box [64, 128]
    make_map(fn, &tmB, wp, IN_F, OUT_F, 64, TILE_N);   // B: [K, N], box [64, 128]

    int nsm = 148;
    cudaDeviceGetAttribute(&nsm, cudaDevAttrMultiProcessorCount, 0);

    cudaFuncSetAttribute(qlin_gemm_kernel, cudaFuncAttributeMaxDynamicSharedMemorySize,
                         SMEM_TOTAL);
    qlin_gemm_kernel<<<2 * nsm, 256, SMEM_TOTAL>>>(tmA, tmB, scales, bias, out);
}

// round 12
// speedup vs baseline: 1.6902x; 1.6902x over previous
#include <cuda_runtime.h>
#include <cuda.h>
#include <cuda_fp16.h>
#include <cstdint>
#include <cstring>

// ---------------- problem constants ----------------
#define TOKENS 8192
#define IN_F   4096
#define OUT_F  11008

// ---------------- GEMM tiling ----------------
constexpr int TILE_M = 256;            // CTA M
constexpr int TILE_N = 128;            // CTA N
constexpr int KC     = 128;            // K elems per stage (2 x 64-col SW128 chunks)
constexpr int NKIT   = IN_F / KC;      // 32  (power of two: f>>5 / f&31)
constexpr int S      = 2;              // pipeline stages (ping-pong)

constexpr int NT_M   = TOKENS / TILE_M;   // 32 (power of two)
constexpr int NT_N   = OUT_F / TILE_N;    // 86
constexpr int NTILES = NT_M * NT_N;       // 2752

// ---------------- SMEM layout ----------------
constexpr int SMEM_TILES   = 1024;                 // 1024-aligned for SW128
constexpr int A_CHUNK      = TILE_M * 128;         // 32768 (64 k-cols)
constexpr int B_CHUNK      = TILE_N * 128;         // 16384
constexpr int A_BYTES      = 2 * A_CHUNK;          // 65536
constexpr int B_BYTES      = 2 * B_CHUNK;          // 32768
constexpr int STAGE_BYTES  = A_BYTES + B_BYTES;    // 98304
constexpr int SMEM_TOTAL   = SMEM_TILES + S * STAGE_BYTES;  // 197632

// ---------------- scratch (fp16 copies) ----------------
__device__ __align__(1024) __half g_x16[(size_t)TOKENS * IN_F];
__device__ __align__(1024) __half g_w16[(size_t)OUT_F * IN_F];

template <int V> struct IC { static constexpr int value = V; };

// ---------------- PTX helpers ----------------
__device__ __forceinline__ uint32_t smem_u32(const void* p) {
    uint32_t a;
    asm("{ .reg .u64 t; cvta.to.shared.u64 t, %1; cvt.u32.u64 %0, t; }" : "=r"(a) : "l"(p));
    return a;
}

#define MBAR_INIT(a, c) \
    asm volatile("mbarrier.init.shared.b64 [%0], %1;" :: "r"(a), "r"((uint32_t)(c)) : "memory")

#define MBAR_EXPECT_TX(a, b) \
    asm volatile("mbarrier.arrive.expect_tx.shared.b64 _, [%0], %1;" :: "r"(a), "r"((uint32_t)(b)) : "memory")

#define MBAR_ARRIVE(a) \
    asm volatile("mbarrier.arrive.shared.b64 _, [%0];" :: "r"(a) : "memory")

#define MBAR_WAIT(a, ph) do {                                                          \
    uint32_t _m = (a); uint32_t _p = (uint32_t)(ph); uint32_t _d;                      \
    asm volatile("{\n .reg .pred p;\n"                                                 \
                 " mbarrier.try_wait.parity.acquire.cta.shared::cta.b64 p, [%1], %2;\n" \
                 " selp.b32 %0, 1, 0, p;\n}" : "=r"(_d) : "r"(_m), "r"(_p) : "memory"); \
    if (!_d) {                                                                         \
        asm volatile("{\n .reg .pred P1;\n"                                            \
                     "WL_%=:\n"                                                         \
                     " mbarrier.try_wait.parity.acquire.cta.shared::cta.b64 P1, [%0], %1, 0x989680;\n" \
                     " @P1 bra.uni WD_%=;\n bra.uni WL_%=;\nWD_%=:\n}"                  \
                     :: "r"(_m), "r"(_p) : "memory");                                   \
    }                                                                                   \
} while (0)

__device__ __forceinline__ void tma2d(uint32_t dst, const CUtensorMap* m, int cx, int cy,
                                      uint32_t bar) {
    asm volatile(
        "cp.async.bulk.tensor.2d.shared::cta.global.tile.mbarrier::complete_tx::bytes "
        "[%0], [%1, {%2, %3}], [%4];"
        :: "r"(dst), "l"(m), "r"(cx), "r"(cy), "r"(bar) : "memory");
}

__device__ __forceinline__ void ldsm4(uint32_t* r, uint32_t addr) {
    asm volatile("ldmatrix.sync.aligned.m8n8.x4.shared.b16 {%0,%1,%2,%3}, [%4];"
                 : "=r"(r[0]), "=r"(r[1]), "=r"(r[2]), "=r"(r[3]) : "r"(addr));
}

__device__ __forceinline__ void mma16816(float* c, const uint32_t* a, const uint32_t* b) {
    asm volatile(
        "mma.sync.aligned.m16n8k16.row.col.f32.f16.f16.f32 "
        "{%0,%1,%2,%3}, {%4,%5,%6,%7}, {%8,%9}, {%0,%1,%2,%3};"
        : "+f"(c[0]), "+f"(c[1]), "+f"(c[2]), "+f"(c[3])
        : "r"(a[0]), "r"(a[1]), "r"(a[2]), "r"(a[3]), "r"(b[0]), "r"(b[1]));
}

// SW128: XOR 16B-column index with (row & 7)
__device__ __forceinline__ uint32_t sw128(uint32_t off) {
    return off ^ ((off >> 3) & 0x70);
}

// ---------------- fused conversion kernel (single launch) ----------------
// x: fp32 -> fp16 ; w: int32 (harness-upcast int8) -> fp16
__global__ void __launch_bounds__(256) cvt_all_kernel(const float4* __restrict__ x,
                                                      uint2* __restrict__ ox, int n4x,
                                                      const int4* __restrict__ w,
                                                      uint2* __restrict__ ow, int n4w) {
    int i = blockIdx.x * blockDim.x + threadIdx.x;
    if (i < n4x) {
        float4 v = x[i];
        __half2 a = __floats2half2_rn(v.x, v.y);
        __half2 b = __floats2half2_rn(v.z, v.w);
        uint2 u;
        memcpy(&u.x, &a, 4);
        memcpy(&u.y, &b, 4);
        ox[i] = u;
    } else {
        int j = i - n4x;
        if (j < n4w) {
            int4 v = w[j];
            __half2 a = __floats2half2_rn((float)v.x, (float)v.y);
            __half2 b = __floats2half2_rn((float)v.z, (float)v.w);
            uint2 u;
            memcpy(&u.x, &a, 4);
            memcpy(&u.y, &b, 4);
            ow[j] = u;
        }
    }
}

// ---------------- main GEMM kernel (persistent, TMA + HMMA, balanced tail) ----
__global__ void __launch_bounds__(256, 1)
qlin_gemm_kernel(const __grid_constant__ CUtensorMap tmA,
                 const __grid_constant__ CUtensorMap tmB,
                 const float* __restrict__ scales,
                 const float* __restrict__ bias,
                 float* __restrict__ out) {
    extern __shared__ __align__(1024) char smem[];
    const uint32_t sb = smem_u32(smem);
    const int tid  = threadIdx.x;
    const int wid  = tid >> 5;
    const int lane = tid & 31;
    const int warp_m = wid >> 1;     // 0..3
    const int warp_n = wid & 1;      // 0..1

    const int bid  = blockIdx.x;
    const int ncta = gridDim.x;

#define FULL_BAR(s)  (sb + (s) * 16)
#define EMPTY_BAR(s) (sb + (s) * 16 + 8)
#define A_OFF(s)     (SMEM_TILES + (s) * STAGE_BYTES)
#define B_OFF(s)     (A_OFF(s) + A_BYTES)

    if (tid == 0) {
        #pragma unroll
        for (int s = 0; s < S; s++) {
            MBAR_INIT(FULL_BAR(s), 1);
            MBAR_INIT(EMPTY_BAR(s), 8);
        }
    }
    __syncthreads();

    // ---- tile schedule: q full tiles per CTA + balanced leftover ----
    const int q = NTILES / ncta;            // 18 @ ncta=152
    const int r = NTILES % ncta;            // 16
    const bool balanced   = (2 * r <= ncta);
    const bool has_half   = balanced && (bid < 2 * r);
    const bool has_exfull = !balanced && (bid < r);
    const int  extra_t    = balanced ? (q * ncta + (bid >> 1)) : (q * ncta + bid);
    const int  extra_moff = balanced ? ((bid & 1) * 128) : 0;
    const int  my_total   = (q + ((has_half || has_exfull) ? 1 : 0)) * NKIT;

    // prologue: issue global stage 0 (first full tile, kt=0)
    if (tid == 0) {
        int t0 = bid;
        int m0 = (t0 & (NT_M - 1)) * TILE_M;
        int n0 = (t0 >> 5) * TILE_N;
        MBAR_EXPECT_TX(FULL_BAR(0), STAGE_BYTES);
        tma2d(sb + A_OFF(0),           &tmA, 0,  m0, FULL_BAR(0));
        tma2d(sb + A_OFF(0) + A_CHUNK, &tmA, 64, m0, FULL_BAR(0));
        tma2d(sb + B_OFF(0),           &tmB, 0,  n0, FULL_BAR(0));
        tma2d(sb + B_OFF(0) + B_CHUNK, &tmB, 64, n0, FULL_BAR(0));
    }

    // B-fragment base offsets (fixed across tiles)
    uint32_t bRow[4];
    #pragma unroll
    for (int n2 = 0; n2 < 4; n2++)
        bRow[n2] = (uint32_t)(warp_n * 64 + n2 * 16 + (lane & 7) + ((lane >> 4) << 3)) * 128 +
                   (((lane >> 3) & 1) << 4);

    float acc[4][8][4];
    #pragma unroll
    for (int mt = 0; mt < 4; mt++)
        #pragma unroll
        for (int nt = 0; nt < 8; nt++)
            #pragma unroll
            for (int j = 0; j < 4; j++) acc[mt][nt][j] = 0.f;

    int g = 0;   // continuous global stage counter

    auto run_tile = [&](int tile_m, int tile_n, int moff, auto mtc_c) {
        constexpr int MTC = decltype(mtc_c)::value;      // 4 (full) or 2 (half-M)
        constexpr int RPW = (MTC == 4) ? 64 : 32;        // rows per warp_m

        uint32_t aRow[MTC];
        #pragma unroll
        for (int mt = 0; mt < MTC; mt++)
            aRow[mt] = (uint32_t)(moff + warp_m * RPW + mt * 16 + (lane & 15)) * 128 +
                       ((lane >> 4) << 4);

        for (int kt = 0; kt < NKIT; kt++, g++) {
            // producer: issue fill for global stage g+1
            if (tid == 0) {
                int f = g + 1;
                if (f < my_total) {
                    int fs = f & 1;
                    if (f >= S) MBAR_WAIT(EMPTY_BAR(fs), ((f >> 1) - 1) & 1);
                    int ft_i = f >> 5;
                    int ft   = (ft_i < q) ? (bid + ft_i * ncta) : extra_t;
                    int fkt  = (f & (NKIT - 1)) * KC;
                    int fm   = (ft & (NT_M - 1)) * TILE_M;
                    int fn   = (ft >> 5) * TILE_N;
                    MBAR_EXPECT_TX(FULL_BAR(fs), STAGE_BYTES);
                    tma2d(sb + A_OFF(fs),           &tmA, fkt,      fm, FULL_BAR(fs));
                    tma2d(sb + A_OFF(fs) + A_CHUNK, &tmA, fkt + 64, fm, FULL_BAR(fs));
                    tma2d(sb + B_OFF(fs),           &tmB, fkt,      fn, FULL_BAR(fs));
                    tma2d(sb + B_OFF(fs) + B_CHUNK, &tmB, fkt + 64, fn, FULL_BAR(fs));
                }
            }

            const int st = g & 1;
            MBAR_WAIT(FULL_BAR(st), (g >> 1) & 1);

            #pragma unroll
            for (int ch = 0; ch < 2; ch++) {
                const uint32_t aT = sb + A_OFF(st) + ch * A_CHUNK;
                const uint32_t bT = sb + B_OFF(st) + ch * B_CHUNK;
                #pragma unroll
                for (int kk = 0; kk < 4; kk++) {
                    uint32_t a[MTC][4], b[4][4];
                    #pragma unroll
                    for (int mt = 0; mt < MTC; mt++)
                        ldsm4(a[mt], aT + sw128(aRow[mt] + kk * 32));
                    #pragma unroll
                    for (int n2 = 0; n2 < 4; n2++)
                        ldsm4(b[n2], bT + sw128(bRow[n2] + kk * 32));
                    #pragma unroll
                    for (int mt = 0; mt < MTC; mt++)
                        #pragma unroll
                        for (int nt = 0; nt < 8; nt++)
                            mma16816(acc[mt][nt], a[mt], &b[nt >> 1][(nt & 1) * 2]);
                }
            }

            if (lane == 0) MBAR_ARRIVE(EMPTY_BAR(st));
        }

        // per-tile epilogue (next tile's TMA already in flight)
        #pragma unroll
        for (int nt = 0; nt < 8; nt++) {
            const int lc = tile_n + warp_n * 64 + nt * 8 + 2 * (lane & 3);
            const float s0 = __ldg(scales + lc);
            const float s1 = __ldg(scales + lc + 1);
            const float b0 = __ldg(bias + lc);
            const float b1 = __ldg(bias + lc + 1);
            #pragma unroll
            for (int mt = 0; mt < MTC; mt++) {
                const int r0 = tile_m + moff + warp_m * RPW + mt * 16 + (lane >> 2);
                float* p0 = out + (size_t)r0 * OUT_F + lc;
                float* p1 = p0 + (size_t)8 * OUT_F;
                float2 v0, v1;
                v0.x = fmaf(acc[mt][nt][0], s0, b0);
                v0.y = fmaf(acc[mt][nt][1], s1, b1);
                v1.x = fmaf(acc[mt][nt][2], s0, b0);
                v1.y = fmaf(acc[mt][nt][3], s1, b1);
                __stcs(reinterpret_cast<float2*>(p0), v0);
                __stcs(reinterpret_cast<float2*>(p1), v1);
            }
        }

        // reset used accumulators
        #pragma unroll
        for (int mt = 0; mt < MTC; mt++)
            #pragma unroll
            for (int nt = 0; nt < 8; nt++)
                #pragma unroll
                for (int j = 0; j < 4; j++) acc[mt][nt][j] = 0.f;
    };

    for (int ti = 0; ti < q; ti++) {
        const int t = bid + ti * ncta;
        run_tile((t & (NT_M - 1)) * TILE_M, (t >> 5) * TILE_N, 0, IC<4>{});
    }
    if (has_half)
        run_tile((extra_t & (NT_M - 1)) * TILE_M, (extra_t >> 5) * TILE_N, extra_moff, IC<2>{});
    else if (has_exfull)
        run_tile((extra_t & (NT_M - 1)) * TILE_M, (extra_t >> 5) * TILE_N, 0, IC<4>{});
}

// ---------------- host: tensormap + launch ----------------
typedef CUresult (*PFN_tmapenc)(CUtensorMap*, CUtensorMapDataType, cuuint32_t, void*,
                                const cuuint64_t*, const cuuint64_t*, const cuuint32_t*,
                                const cuuint32_t*, CUtensorMapInterleave, CUtensorMapSwizzle,
                                CUtensorMapL2promotion, CUtensorMapFloatOOBfill);

static PFN_tmapenc get_tmap_fn() {
    void* fp = nullptr;
    cudaDriverEntryPointQueryResult qr;
#if CUDART_VERSION >= 12050
    cudaGetDriverEntryPointByVersion("cuTensorMapEncodeTiled", &fp, 12000, cudaEnableDefault, &qr);
#else
    cudaGetDriverEntryPoint("cuTensorMapEncodeTiled", &fp, cudaEnableDefault, &qr);
#endif
    return (PFN_tmapenc)fp;
}

static void make_map(PFN_tmapenc fn, CUtensorMap* m, void* base, uint64_t d0, uint64_t d1,
                     uint32_t b0, uint32_t b1) {
    cuuint64_t dims[2]    = {d0, d1};
    cuuint64_t strides[1] = {d0 * 2};  // bytes (fp16)
    cuuint32_t box[2]     = {b0, b1};
    cuuint32_t es[2]      = {1, 1};
    fn(m, CU_TENSOR_MAP_DATA_TYPE_FLOAT16, 2, base, dims, strides, box, es,
       CU_TENSOR_MAP_INTERLEAVE_NONE, CU_TENSOR_MAP_SWIZZLE_128B,
       CU_TENSOR_MAP_L2_PROMOTION_L2_128B, CU_TENSOR_MAP_FLOAT_OOB_FILL_NONE);
}

extern "C" void kernel_launch(void* const* d_in, const int* in_sizes, int n_in,
                              void* d_out, int out_size) {
    const float* x      = (const float*)d_in[0];
    const int4*  w      = (const int4*)d_in[1];   // int32 weights, 4 per int4
    const float* scales = (const float*)d_in[2];
    const float* bias   = (const float*)d_in[3];
    float*       out    = (float*)d_out;

    void* xp = nullptr;
    void* wp = nullptr;
    cudaGetSymbolAddress(&xp, g_x16);
    cudaGetSymbolAddress(&wp, g_w16);

    // fused fp16 conversion pre-pass: ONE launch so the GEMM is every 2nd kernel
    {
        int n4x = TOKENS * IN_F / 4;
        int n4w = OUT_F * IN_F / 4;
        int tot = n4x + n4w;
        cvt_all_kernel<<<(tot + 255) / 256, 256>>>((const float4*)x, (uint2*)xp, n4x,
                                                   w, (uint2*)wp, n4w);
    }

    PFN_tmapenc fn = get_tmap_fn();
    CUtensorMap tmA, tmB;
    make_map(fn, &tmA, xp, IN_F, TOKENS, 64, TILE_M);  // A: [K, M], box [64, 256]
    make_map(fn, &tmB, wp, IN_F, OUT_F, 64, TILE_N);   // B: [K, N], box [64, 128]

    int nsm = 148;
    cudaDeviceGetAttribute(&nsm, cudaDevAttrMultiProcessorCount, 0);

    cudaFuncSetAttribute(qlin_gemm_kernel, cudaFuncAttributeMaxDynamicSharedMemorySize,
                         SMEM_TOTAL);
    qlin_gemm_kernel<<<nsm, 256, SMEM_TOTAL>>>(tmA, tmB, scales, bias, out);
}

// round 13
// speedup vs baseline: 1.7048x; 1.0087x over previous
#include <cuda_runtime.h>
#include <cuda.h>
#include <cuda_fp16.h>
#include <cstdint>
#include <cstring>

// ---------------- problem constants ----------------
#define TOKENS 8192
#define IN_F   4096
#define OUT_F  11008

// ---------------- GEMM tiling ----------------
constexpr int TILE_M = 256;            // CTA M
constexpr int TILE_N = 128;            // CTA N
constexpr int KC     = 128;            // K elems per stage (2 x 64-col SW128 chunks)
constexpr int NKIT   = IN_F / KC;      // 32
constexpr int S      = 2;              // pipeline stages (ping-pong)

constexpr int NT_M   = TOKENS / TILE_M;   // 32 (power of two)
constexpr int NT_N   = OUT_F / TILE_N;    // 86
constexpr int NTILES = NT_M * NT_N;       // 2752

// ---------------- SMEM layout ----------------
// [0 .. 32)  : barriers  full(s)=s*16, empty(s)=s*16+8
// [64]       : next-ticket handoff (int)
// [1024 ..)  : tile stages
constexpr int SMEM_TILES   = 1024;                 // 1024-aligned for SW128
constexpr int A_CHUNK      = TILE_M * 128;         // 32768 (64 k-cols)
constexpr int B_CHUNK      = TILE_N * 128;         // 16384
constexpr int A_BYTES      = 2 * A_CHUNK;          // 65536
constexpr int B_BYTES      = 2 * B_CHUNK;          // 32768
constexpr int STAGE_BYTES  = A_BYTES + B_BYTES;    // 98304
constexpr int SMEM_TOTAL   = SMEM_TILES + S * STAGE_BYTES;  // 197632

// ---------------- scratch (fp16 copies) + work-steal counter ----------------
__device__ __align__(1024) __half g_x16[(size_t)TOKENS * IN_F];
__device__ __align__(1024) __half g_w16[(size_t)OUT_F * IN_F];
__device__ int g_ticket;

// ---------------- PTX helpers ----------------
__device__ __forceinline__ uint32_t smem_u32(const void* p) {
    uint32_t a;
    asm("{ .reg .u64 t; cvta.to.shared.u64 t, %1; cvt.u32.u64 %0, t; }" : "=r"(a) : "l"(p));
    return a;
}

#define MBAR_INIT(a, c) \
    asm volatile("mbarrier.init.shared.b64 [%0], %1;" :: "r"(a), "r"((uint32_t)(c)) : "memory")

#define MBAR_EXPECT_TX(a, b) \
    asm volatile("mbarrier.arrive.expect_tx.shared.b64 _, [%0], %1;" :: "r"(a), "r"((uint32_t)(b)) : "memory")

#define MBAR_ARRIVE(a) \
    asm volatile("mbarrier.arrive.shared.b64 _, [%0];" :: "r"(a) : "memory")

#define MBAR_WAIT(a, ph) do {                                                          \
    uint32_t _m = (a); uint32_t _p = (uint32_t)(ph); uint32_t _d;                      \
    asm volatile("{\n .reg .pred p;\n"                                                 \
                 " mbarrier.try_wait.parity.acquire.cta.shared::cta.b64 p, [%1], %2;\n" \
                 " selp.b32 %0, 1, 0, p;\n}" : "=r"(_d) : "r"(_m), "r"(_p) : "memory"); \
    if (!_d) {                                                                         \
        asm volatile("{\n .reg .pred P1;\n"                                            \
                     "WL_%=:\n"                                                         \
                     " mbarrier.try_wait.parity.acquire.cta.shared::cta.b64 P1, [%0], %1, 0x989680;\n" \
                     " @P1 bra.uni WD_%=;\n bra.uni WL_%=;\nWD_%=:\n}"                  \
                     :: "r"(_m), "r"(_p) : "memory");                                   \
    }                                                                                   \
} while (0)

__device__ __forceinline__ void tma2d(uint32_t dst, const CUtensorMap* m, int cx, int cy,
                                      uint32_t bar) {
    asm volatile(
        "cp.async.bulk.tensor.2d.shared::cta.global.tile.mbarrier::complete_tx::bytes "
        "[%0], [%1, {%2, %3}], [%4];"
        :: "r"(dst), "l"(m), "r"(cx), "r"(cy), "r"(bar) : "memory");
}

__device__ __forceinline__ void ldsm4(uint32_t* r, uint32_t addr) {
    asm volatile("ldmatrix.sync.aligned.m8n8.x4.shared.b16 {%0,%1,%2,%3}, [%4];"
                 : "=r"(r[0]), "=r"(r[1]), "=r"(r[2]), "=r"(r[3]) : "r"(addr));
}

__device__ __forceinline__ void mma16816(float* c, const uint32_t* a, const uint32_t* b) {
    asm volatile(
        "mma.sync.aligned.m16n8k16.row.col.f32.f16.f16.f32 "
        "{%0,%1,%2,%3}, {%4,%5,%6,%7}, {%8,%9}, {%0,%1,%2,%3};"
        : "+f"(c[0]), "+f"(c[1]), "+f"(c[2]), "+f"(c[3])
        : "r"(a[0]), "r"(a[1]), "r"(a[2]), "r"(a[3]), "r"(b[0]), "r"(b[1]));
}

// SW128: XOR 16B-column index with (row & 7)
__device__ __forceinline__ uint32_t sw128(uint32_t off) {
    return off ^ ((off >> 3) & 0x70);
}

// ---------------- fused conversion kernel (single launch) ----------------
// x: fp32 -> fp16 ; w: int32 (harness-upcast int8) -> fp16 ; resets ticket
__global__ void __launch_bounds__(256) cvt_all_kernel(const float4* __restrict__ x,
                                                      uint2* __restrict__ ox, int n4x,
                                                      const int4* __restrict__ w,
                                                      uint2* __restrict__ ow, int n4w,
                                                      int ticket0) {
    if (blockIdx.x == 0 && threadIdx.x == 0) g_ticket = ticket0;
    int i = blockIdx.x * blockDim.x + threadIdx.x;
    if (i < n4x) {
        float4 v = x[i];
        __half2 a = __floats2half2_rn(v.x, v.y);
        __half2 b = __floats2half2_rn(v.z, v.w);
        uint2 u;
        memcpy(&u.x, &a, 4);
        memcpy(&u.y, &b, 4);
        ox[i] = u;
    } else {
        int j = i - n4x;
        if (j < n4w) {
            int4 v = w[j];
            __half2 a = __floats2half2_rn((float)v.x, (float)v.y);
            __half2 b = __floats2half2_rn((float)v.z, (float)v.w);
            uint2 u;
            memcpy(&u.x, &a, 4);
            memcpy(&u.y, &b, 4);
            ow[j] = u;
        }
    }
}

// ---------------- main GEMM kernel (persistent + work stealing) ----------------
__global__ void __launch_bounds__(256, 1)
qlin_gemm_kernel(const __grid_constant__ CUtensorMap tmA,
                 const __grid_constant__ CUtensorMap tmB,
                 const float* __restrict__ scales,
                 const float* __restrict__ bias,
                 float* __restrict__ out) {
    extern __shared__ __align__(1024) char smem[];
    const uint32_t sb = smem_u32(smem);
    const int tid  = threadIdx.x;
    const int wid  = tid >> 5;
    const int lane = tid & 31;
    const int warp_m = wid >> 1;     // 0..3  (64 rows each)
    const int warp_n = wid & 1;      // 0..1  (64 cols each)

    const int bid = blockIdx.x;

#define FULL_BAR(s)  (sb + (s) * 16)
#define EMPTY_BAR(s) (sb + (s) * 16 + 8)
#define A_OFF(s)     (SMEM_TILES + (s) * STAGE_BYTES)
#define B_OFF(s)     (A_OFF(s) + A_BYTES)

    int* s_next = reinterpret_cast<int*>(smem + 64);

    if (tid == 0) {
        #pragma unroll
        for (int s = 0; s < S; s++) {
            MBAR_INIT(FULL_BAR(s), 1);
            MBAR_INIT(EMPTY_BAR(s), 8);
        }
        *s_next = NTILES;  // sentinel until first fetch
    }
    __syncthreads();

    // prologue: issue stage 0 of first (static) tile
    if (tid == 0) {
        int m0 = (bid & (NT_M - 1)) * TILE_M;
        int n0 = (bid >> 5) * TILE_N;
        MBAR_EXPECT_TX(FULL_BAR(0), STAGE_BYTES);
        tma2d(sb + A_OFF(0),           &tmA, 0,  m0, FULL_BAR(0));
        tma2d(sb + A_OFF(0) + A_CHUNK, &tmA, 64, m0, FULL_BAR(0));
        tma2d(sb + B_OFF(0),           &tmB, 0,  n0, FULL_BAR(0));
        tma2d(sb + B_OFF(0) + B_CHUNK, &tmB, 64, n0, FULL_BAR(0));
    }

    // fragment base byte offsets (tile-invariant; chunk-relative, before swizzle)
    uint32_t aRow[4], bRow[4];
    #pragma unroll
    for (int mt = 0; mt < 4; mt++)
        aRow[mt] = (uint32_t)(warp_m * 64 + mt * 16 + (lane & 15)) * 128 +
                   ((lane >> 4) << 4);
    #pragma unroll
    for (int n2 = 0; n2 < 4; n2++)
        bRow[n2] = (uint32_t)(warp_n * 64 + n2 * 16 + (lane & 7) + ((lane >> 4) << 3)) * 128 +
                   (((lane >> 3) & 1) << 4);

    float acc[4][8][4];
    #pragma unroll
    for (int mt = 0; mt < 4; mt++)
        #pragma unroll
        for (int nt = 0; nt < 8; nt++)
            #pragma unroll
            for (int j = 0; j < 4; j++) acc[mt][nt][j] = 0.f;

    // consumer ring state
    int cst = 0, cph = 0;
    // producer (tid 0) lookahead state: streams stages one ahead of consumer
    int p_cur = bid;   // ticket currently being streamed
    int p_kt  = 1;     // next k-iter to issue within p_cur (stage 0 done in prologue)
    int p_f   = 1;     // global issue index (for empty-bar parity)

    int cur = bid;     // consumer's current tile
    for (;;) {
        const int tile_m = (cur & (NT_M - 1)) * TILE_M;
        const int tile_n = (cur >> 5) * TILE_N;

        for (int kt = 0; kt < NKIT; kt++) {
            // producer: issue next stage (one ahead); steal a new ticket at boundary
            if (tid == 0 && p_cur < NTILES) {
                if (p_kt == NKIT) {
                    p_cur  = atomicAdd(&g_ticket, 1);
                    *s_next = p_cur;   // visible to all after tile-end __syncthreads
                    p_kt = 0;
                }
                if (p_cur < NTILES) {
                    int fs = p_f & 1;
                    if (p_f >= S) MBAR_WAIT(EMPTY_BAR(fs), ((p_f >> 1) - 1) & 1);
                    int fkt = p_kt * KC;
                    int fm  = (p_cur & (NT_M - 1)) * TILE_M;
                    int fn  = (p_cur >> 5) * TILE_N;
                    MBAR_EXPECT_TX(FULL_BAR(fs), STAGE_BYTES);
                    tma2d(sb + A_OFF(fs),           &tmA, fkt,      fm, FULL_BAR(fs));
                    tma2d(sb + A_OFF(fs) + A_CHUNK, &tmA, fkt + 64, fm, FULL_BAR(fs));
                    tma2d(sb + B_OFF(fs),           &tmB, fkt,      fn, FULL_BAR(fs));
                    tma2d(sb + B_OFF(fs) + B_CHUNK, &tmB, fkt + 64, fn, FULL_BAR(fs));
                    p_f++;
                    p_kt++;
                }
            }

            MBAR_WAIT(FULL_BAR(cst), cph);

            #pragma unroll
            for (int ch = 0; ch < 2; ch++) {
                const uint32_t aT = sb + A_OFF(cst) + ch * A_CHUNK;
                const uint32_t bT = sb + B_OFF(cst) + ch * B_CHUNK;
                #pragma unroll
                for (int kk = 0; kk < 4; kk++) {
                    uint32_t a[4][4], b[4][4];
                    #pragma unroll
                    for (int mt = 0; mt < 4; mt++)
                        ldsm4(a[mt], aT + sw128(aRow[mt] + kk * 32));
                    #pragma unroll
                    for (int n2 = 0; n2 < 4; n2++)
                        ldsm4(b[n2], bT + sw128(bRow[n2] + kk * 32));
                    #pragma unroll
                    for (int mt = 0; mt < 4; mt++)
                        #pragma unroll
                        for (int nt = 0; nt < 8; nt++)
                            mma16816(acc[mt][nt], a[mt], &b[nt >> 1][(nt & 1) * 2]);
                }
            }

            if (lane == 0) MBAR_ARRIVE(EMPTY_BAR(cst));
            if (++cst == S) { cst = 0; cph ^= 1; }
        }

        // ---------------- per-tile epilogue (next tile's TMA already in flight) ----
        #pragma unroll
        for (int nt = 0; nt < 8; nt++) {
            const int lc = tile_n + warp_n * 64 + nt * 8 + 2 * (lane & 3);
            const float s0 = __ldg(scales + lc);
            const float s1 = __ldg(scales + lc + 1);
            const float b0 = __ldg(bias + lc);
            const float b1 = __ldg(bias + lc + 1);
            #pragma unroll
            for (int mt = 0; mt < 4; mt++) {
                const int r0 = tile_m + warp_m * 64 + mt * 16 + (lane >> 2);
                float* p0 = out + (size_t)r0 * OUT_F + lc;
                float* p1 = p0 + (size_t)8 * OUT_F;
                float2 v0, v1;
                v0.x = fmaf(acc[mt][nt][0], s0, b0);
                v0.y = fmaf(acc[mt][nt][1], s1, b1);
                v1.x = fmaf(acc[mt][nt][2], s0, b0);
                v1.y = fmaf(acc[mt][nt][3], s1, b1);
                __stcs(reinterpret_cast<float2*>(p0), v0);
                __stcs(reinterpret_cast<float2*>(p1), v1);
            }
        }

        // reset accumulators
        #pragma unroll
        for (int mt = 0; mt < 4; mt++)
            #pragma unroll
            for (int nt = 0; nt < 8; nt++)
                #pragma unroll
                for (int j = 0; j < 4; j++) acc[mt][nt][j] = 0.f;

        __syncthreads();        // orders tid0's *s_next store before everyone's read
        cur = *s_next;
        if (cur >= NTILES) break;
    }
}

// ---------------- host: tensormap + launch ----------------
typedef CUresult (*PFN_tmapenc)(CUtensorMap*, CUtensorMapDataType, cuuint32_t, void*,
                                const cuuint64_t*, const cuuint64_t*, const cuuint32_t*,
                                const cuuint32_t*, CUtensorMapInterleave, CUtensorMapSwizzle,
                                CUtensorMapL2promotion, CUtensorMapFloatOOBfill);

static PFN_tmapenc get_tmap_fn() {
    void* fp = nullptr;
    cudaDriverEntryPointQueryResult qr;
#if CUDART_VERSION >= 12050
    cudaGetDriverEntryPointByVersion("cuTensorMapEncodeTiled", &fp, 12000, cudaEnableDefault, &qr);
#else
    cudaGetDriverEntryPoint("cuTensorMapEncodeTiled", &fp, cudaEnableDefault, &qr);
#endif
    return (PFN_tmapenc)fp;
}

static void make_map(PFN_tmapenc fn, CUtensorMap* m, void* base, uint64_t d0, uint64_t d1,
                     uint32_t b0, uint32_t b1) {
    cuuint64_t dims[2]    = {d0, d1};
    cuuint64_t strides[1] = {d0 * 2};  // bytes (fp16)
    cuuint32_t box[2]     = {b0, b1};
    cuuint32_t es[2]      = {1, 1};
    fn(m, CU_TENSOR_MAP_DATA_TYPE_FLOAT16, 2, base, dims, strides, box, es,
       CU_TENSOR_MAP_INTERLEAVE_NONE, CU_TENSOR_MAP_SWIZZLE_128B,
       CU_TENSOR_MAP_L2_PROMOTION_L2_128B, CU_TENSOR_MAP_FLOAT_OOB_FILL_NONE);
}

extern "C" void kernel_launch(void* const* d_in, const int* in_sizes, int n_in,
                              void* d_out, int out_size) {
    const float* x      = (const float*)d_in[0];
    const int4*  w      = (const int4*)d_in[1];   // int32 weights, 4 per int4
    const float* scales = (const float*)d_in[2];
    const float* bias   = (const float*)d_in[3];
    float*       out    = (float*)d_out;

    void* xp = nullptr;
    void* wp = nullptr;
    cudaGetSymbolAddress(&xp, g_x16);
    cudaGetSymbolAddress(&wp, g_w16);

    int nsm = 148;
    cudaDeviceGetAttribute(&nsm, cudaDevAttrMultiProcessorCount, 0);

    // fused fp16 conversion pre-pass (also resets the work-steal ticket to nsm)
    {
        int n4x = TOKENS * IN_F / 4;
        int n4w = OUT_F * IN_F / 4;
        int tot = n4x + n4w;
        cvt_all_kernel<<<(tot + 255) / 256, 256>>>((const float4*)x, (uint2*)xp, n4x,
                                                   w, (uint2*)wp, n4w, nsm);
    }

    PFN_tmapenc fn = get_tmap_fn();
    CUtensorMap tmA, tmB;
    make_map(fn, &tmA, xp, IN_F, TOKENS, 64, TILE_M);  // A: [K, M], box [64, 256]
    make_map(fn, &tmB, wp, IN_F, OUT_F, 64, TILE_N);   // B: [K, N], box [64, 128]

    cudaFuncSetAttribute(qlin_gemm_kernel, cudaFuncAttributeMaxDynamicSharedMemorySize,
                         SMEM_TOTAL);
    qlin_gemm_kernel<<<nsm, 256, SMEM_TOTAL>>>(tmA, tmB, scales, bias, out);
}